// round 4
// baseline (speedup 1.0000x reference)
#include <cuda_runtime.h>
#include <math.h>

#define NN 50000
#define NE 400000
#define EP (NE + NN)   // edges + self loops (virtual)

// ---------------- one big scratch buffer (device global; no allocations) ----
// offsets in floats
#define O_GSUM   0LL
#define O_GATE   64LL
#define O_INDEG  128LL
#define O_DIS    (O_INDEG + NN)
#define O_GCNXH  (O_DIS + NN)
#define O_AGG1   (O_GCNXH + (long long)NN*64)
#define O_GCNH1  (O_AGG1  + (long long)NN*64)
#define O_GCNH2  (O_GCNH1 + (long long)NN*64)
#define O_AGG2   (O_GCNH2 + (long long)NN*64)
#define O_GATH1  (O_AGG2  + (long long)NN*64)
#define O_AS1    (O_GATH1 + (long long)NN*256)
#define O_AD1    (O_AS1 + (long long)NN*4)
#define O_M1     (O_AD1 + (long long)NN*4)
#define O_D1     (O_M1  + (long long)NN*4)
#define O_GAGG1  (O_D1  + (long long)NN*4)
#define O_GATH2  (O_GAGG1 + (long long)NN*256)
#define O_AS2    (O_GATH2 + (long long)NN*64)
#define O_AD2    (O_AS2 + NN)
#define O_M2     (O_AD2 + NN)
#define O_D2     (O_M2  + NN)
#define O_GAGG2  (O_D2  + NN)
#define O_SXR    (O_GAGG2 + (long long)NN*64)
#define O_SAGGX  (O_SXR   + (long long)NN*64)
#define O_SMEAN  (O_SAGGX + (long long)NN*64)
#define O_SML    (O_SMEAN + (long long)NN*64)
#define O_SH1    (O_SML   + (long long)NN*64)
#define O_SAGG2  (O_SH1   + (long long)NN*64)
#define O_SMEAN2 (O_SAGG2 + (long long)NN*64)
#define O_SML2   (O_SMEAN2+ (long long)NN*64)
#define O_SXR2   (O_SML2  + (long long)NN*64)
#define O_SOUT   (O_SXR2  + (long long)NN*64)
#define SZ_TOTAL (O_SOUT  + (long long)NN*64)

__device__ float g_buf[SZ_TOTAL];

// ---------------- helpers ----------------
__device__ __forceinline__ void atomicMaxF(float* a, float v) {
    if (v >= 0.f) atomicMax((int*)a, __float_as_int(v));
    else          atomicMin((unsigned int*)a, __float_as_uint(v));
}
__device__ __forceinline__ float lrelu(float x) { return x > 0.f ? x : 0.2f * x; }

// ---------------- init ----------------
__global__ void zero_all(float* __restrict__ B) {
    long long i = (long long)blockIdx.x * 256 + threadIdx.x;   // covers NN*256
    B[O_GAGG1 + i] = 0.f;
    if (i < (long long)NN * 64) {
        B[O_AGG1 + i] = 0.f; B[O_AGG2 + i] = 0.f; B[O_GAGG2 + i] = 0.f;
        B[O_SAGGX + i] = 0.f; B[O_SAGG2 + i] = 0.f;
    }
    if (i < NN * 4) { B[O_D1 + i] = 0.f; B[O_M1 + i] = -1e30f; }
    if (i < NN)     { B[O_INDEG + i] = 0.f; B[O_D2 + i] = 0.f; B[O_M2 + i] = -1e30f; }
    if (i < 64)     B[O_GSUM + i] = 0.f;
}

__global__ void degree_kernel(const int* __restrict__ col, float* __restrict__ indeg) {
    int e = blockIdx.x * blockDim.x + threadIdx.x;
    if (e < NE) atomicAdd(&indeg[col[e]], 1.f);
}

__global__ void dis_kernel(const float* __restrict__ indeg, float* __restrict__ dis) {
    int i = blockIdx.x * blockDim.x + threadIdx.x;
    if (i < NN) dis[i] = rsqrtf(indeg[i] + 1.f);
}

// ---------------- gate ----------------
__global__ void colsum_kernel(const float* __restrict__ x, float* __restrict__ gsum) {
    __shared__ float s[256];
    int t = threadIdx.x;
    int c = t & 63, rg = t >> 6;
    float acc = 0.f;
    for (int i = blockIdx.x * 4 + rg; i < NN; i += gridDim.x * 4)
        acc += x[i * 64 + c];
    s[t] = acc;
    __syncthreads();
    if (t < 64) {
        float v = s[t] + s[t + 64] + s[t + 128] + s[t + 192];
        atomicAdd(&gsum[t], v);
    }
}

__global__ void gate_kernel(const float* __restrict__ gsum, float* __restrict__ gate,
                            const float* __restrict__ w1, const float* __restrict__ b1,
                            const float* __restrict__ w2, const float* __restrict__ b2) {
    __shared__ float gm[64], hid[64], o[3];
    int t = threadIdx.x;
    gm[t] = gsum[t] / (float)NN;
    __syncthreads();
    float a = b1[t];
    for (int k = 0; k < 64; k++) a += gm[k] * w1[k * 64 + t];
    hid[t] = fmaxf(a, 0.f);
    __syncthreads();
    if (t < 3) {
        float s = b2[t];
        for (int k = 0; k < 64; k++) s += hid[k] * w2[k * 3 + t];
        o[t] = s;
    }
    __syncthreads();
    if (t == 0) {
        float mx = fmaxf(o[0], fmaxf(o[1], o[2]));
        float e0 = expf(o[0] - mx), e1 = expf(o[1] - mx), e2 = expf(o[2] - mx);
        float s = e0 + e1 + e2;
        gate[0] = e0 / s; gate[1] = e1 / s; gate[2] = e2 / s;
    }
}

// ---------------- generic small GEMM: C[n,dout] = A[n,DIN] @ W[DIN,dout] ----
template <int DIN>
__global__ void gemm_kernel(const float* __restrict__ A, const float* __restrict__ W,
                            float* __restrict__ C, int n, int dout) {
    __shared__ float sA[4][DIN];
    int row0 = blockIdx.x * 4;
    int col = blockIdx.y * 64 + threadIdx.x;
    int tid = threadIdx.y * 64 + threadIdx.x;
    for (int idx = tid; idx < 4 * DIN; idx += 256) {
        int r = idx / DIN, k = idx % DIN;
        sA[r][k] = (row0 + r < n) ? A[(long long)(row0 + r) * DIN + k] : 0.f;
    }
    __syncthreads();
    int row = row0 + threadIdx.y;
    if (row < n) {
        float acc = 0.f;
#pragma unroll 16
        for (int k = 0; k < DIN; k++) acc += sA[threadIdx.y][k] * W[k * dout + col];
        C[(long long)row * dout + col] = acc;
    }
}

// ---------------- GCN ----------------
__global__ void gcn_edge_agg(const int* __restrict__ row, const int* __restrict__ col,
                             const float* __restrict__ dis,
                             const float* __restrict__ h, float* __restrict__ agg) {
    int e = blockIdx.x * 4 + threadIdx.y;
    int r, c;
    if (e < NE) { r = row[e]; c = col[e]; } else { r = c = e - NE; }
    float nrm = dis[r] * dis[c];
    int f = threadIdx.x;
    atomicAdd(&agg[c * 64 + f], h[r * 64 + f] * nrm);
}

__global__ void gcn_post1(const float* __restrict__ agg1, float* __restrict__ h1,
                          const float* __restrict__ b, const float* __restrict__ gamma,
                          const float* __restrict__ beta) {
    int i = blockIdx.x * 256 + threadIdx.x;
    if (i >= NN * 64) return;
    int f = i & 63;
    float scale = gamma[f] * rsqrtf(1.f + 1e-5f);
    float v = (agg1[i] + b[f]) * scale + beta[f];
    h1[i] = fmaxf(v, 0.f);
}

// ---------------- GAT ----------------
__global__ void gat_att1(const float* __restrict__ gath1,
                         float* __restrict__ as1, float* __restrict__ ad1,
                         const float* __restrict__ asrc, const float* __restrict__ adst) {
    int n = blockIdx.x;
    int t = threadIdx.x;
    float v = gath1[(long long)n * 256 + t];
    __shared__ float ss[256], sd[256];
    ss[t] = v * asrc[t];
    sd[t] = v * adst[t];
    __syncthreads();
    for (int s = 32; s > 0; s >>= 1) {
        if ((t & 63) < s) { ss[t] += ss[t + s]; sd[t] += sd[t + s]; }
        __syncthreads();
    }
    if ((t & 63) == 0) {
        as1[n * 4 + (t >> 6)] = ss[t];
        ad1[n * 4 + (t >> 6)] = sd[t];
    }
}

__global__ void gat_max1(const int* __restrict__ row, const int* __restrict__ col,
                         const float* __restrict__ as1, const float* __restrict__ ad1,
                         float* __restrict__ m1) {
    int e = blockIdx.x * blockDim.x + threadIdx.x;
    if (e >= EP) return;
    int r, c;
    if (e < NE) { r = row[e]; c = col[e]; } else { r = c = e - NE; }
#pragma unroll
    for (int h = 0; h < 4; h++) {
        float x = lrelu(as1[r * 4 + h] + ad1[c * 4 + h]);
        atomicMaxF(&m1[c * 4 + h], x);
    }
}

__global__ void gat_den1(const int* __restrict__ row, const int* __restrict__ col,
                         const float* __restrict__ as1, const float* __restrict__ ad1,
                         const float* __restrict__ m1, float* __restrict__ d1) {
    int e = blockIdx.x * blockDim.x + threadIdx.x;
    if (e >= EP) return;
    int r, c;
    if (e < NE) { r = row[e]; c = col[e]; } else { r = c = e - NE; }
#pragma unroll
    for (int h = 0; h < 4; h++) {
        float x = lrelu(as1[r * 4 + h] + ad1[c * 4 + h]);
        atomicAdd(&d1[c * 4 + h], expf(x - m1[c * 4 + h]));
    }
}

__global__ void gat_agg1k(const int* __restrict__ row, const int* __restrict__ col,
                          const float* __restrict__ as1, const float* __restrict__ ad1,
                          const float* __restrict__ m1, const float* __restrict__ d1,
                          const float* __restrict__ gath1, float* __restrict__ gagg1) {
    int e = blockIdx.x;
    int t = threadIdx.x;
    int r, c;
    if (e < NE) { r = row[e]; c = col[e]; } else { r = c = e - NE; }
    int h = t >> 6;
    float x = lrelu(as1[r * 4 + h] + ad1[c * 4 + h]);
    float alpha = expf(x - m1[c * 4 + h]) / d1[c * 4 + h];
    atomicAdd(&gagg1[(long long)c * 256 + t], gath1[(long long)r * 256 + t] * alpha);
}

__global__ void gat_post1(float* __restrict__ gagg1, const float* __restrict__ b) {
    long long i = (long long)blockIdx.x * 256 + threadIdx.x;
    if (i >= (long long)NN * 256) return;
    float v = gagg1[i] + b[i & 255];
    gagg1[i] = v > 0.f ? v : (expf(v) - 1.f);   // ELU
}

__global__ void gat_att2(const float* __restrict__ gath2,
                         float* __restrict__ as2, float* __restrict__ ad2,
                         const float* __restrict__ asrc, const float* __restrict__ adst) {
    int n = blockIdx.x * 4 + threadIdx.y;
    int t = threadIdx.x;
    __shared__ float ss[4][64], sd[4][64];
    float v = gath2[n * 64 + t];
    ss[threadIdx.y][t] = v * asrc[t];
    sd[threadIdx.y][t] = v * adst[t];
    __syncthreads();
    for (int s = 32; s > 0; s >>= 1) {
        if (t < s) {
            ss[threadIdx.y][t] += ss[threadIdx.y][t + s];
            sd[threadIdx.y][t] += sd[threadIdx.y][t + s];
        }
        __syncthreads();
    }
    if (t == 0) { as2[n] = ss[threadIdx.y][0]; ad2[n] = sd[threadIdx.y][0]; }
}

__global__ void gat_max2(const int* __restrict__ row, const int* __restrict__ col,
                         const float* __restrict__ as2, const float* __restrict__ ad2,
                         float* __restrict__ m2) {
    int e = blockIdx.x * blockDim.x + threadIdx.x;
    if (e >= EP) return;
    int r, c;
    if (e < NE) { r = row[e]; c = col[e]; } else { r = c = e - NE; }
    atomicMaxF(&m2[c], lrelu(as2[r] + ad2[c]));
}

__global__ void gat_den2(const int* __restrict__ row, const int* __restrict__ col,
                         const float* __restrict__ as2, const float* __restrict__ ad2,
                         const float* __restrict__ m2, float* __restrict__ d2) {
    int e = blockIdx.x * blockDim.x + threadIdx.x;
    if (e >= EP) return;
    int r, c;
    if (e < NE) { r = row[e]; c = col[e]; } else { r = c = e - NE; }
    float x = lrelu(as2[r] + ad2[c]);
    atomicAdd(&d2[c], expf(x - m2[c]));
}

__global__ void gat_agg2k(const int* __restrict__ row, const int* __restrict__ col,
                          const float* __restrict__ as2, const float* __restrict__ ad2,
                          const float* __restrict__ m2, const float* __restrict__ d2,
                          const float* __restrict__ gath2, float* __restrict__ gagg2) {
    int e = blockIdx.x * 4 + threadIdx.y;
    int r, c;
    if (e < NE) { r = row[e]; c = col[e]; } else { r = c = e - NE; }
    float x = lrelu(as2[r] + ad2[c]);
    float alpha = expf(x - m2[c]) / d2[c];
    int f = threadIdx.x;
    atomicAdd(&gagg2[c * 64 + f], gath2[r * 64 + f] * alpha);
}

// ---------------- SAGE ----------------
__global__ void sage_edge_agg(const int* __restrict__ row, const int* __restrict__ col,
                              const float* __restrict__ h, float* __restrict__ agg) {
    int e = blockIdx.x * 4 + threadIdx.y;
    int r = row[e], c = col[e];
    int f = threadIdx.x;
    atomicAdd(&agg[c * 64 + f], h[r * 64 + f]);
}

__global__ void sage_mean(const float* __restrict__ src, float* __restrict__ dst,
                          const float* __restrict__ indeg) {
    int i = blockIdx.x * 256 + threadIdx.x;
    if (i >= NN * 64) return;
    dst[i] = src[i] / fmaxf(indeg[i >> 6], 1.f);
}

__global__ void sage_post(const float* __restrict__ ml, const float* __restrict__ bl,
                          const float* __restrict__ xr, float* __restrict__ out, int dorelu) {
    int n = blockIdx.x * 4 + threadIdx.y;
    int f = threadIdx.x;
    float v = ml[n * 64 + f] + bl[f] + xr[n * 64 + f];
    __shared__ float red[4][64];
    red[threadIdx.y][f] = v * v;
    __syncthreads();
    for (int s = 32; s > 0; s >>= 1) {
        if (f < s) red[threadIdx.y][f] += red[threadIdx.y][f + s];
        __syncthreads();
    }
    float nrm = sqrtf(red[threadIdx.y][0]);
    float o = v / fmaxf(nrm, 1e-12f);
    if (dorelu) o = fmaxf(o, 0.f);
    out[n * 64 + f] = o;
}

// ---------------- final combine ----------------
__global__ void combine_kernel(float* __restrict__ out, const float* __restrict__ gate,
                               const float* __restrict__ agg2, const float* __restrict__ gagg2,
                               const float* __restrict__ sout,
                               const float* __restrict__ gcn_b2, const float* __restrict__ gat_b2) {
    int i = blockIdx.x * 256 + threadIdx.x;
    if (i >= NN * 64) return;
    int f = i & 63;
    float w0 = gate[0], w1 = gate[1], w2 = gate[2];
    float gcn = agg2[i] + gcn_b2[f];
    float gat = gagg2[i] + gat_b2[f];
    out[i] = w0 * gcn + w1 * gat + w2 * sout[i];
}

// ---------------- launch ----------------
extern "C" void kernel_launch(void* const* d_in, const int* in_sizes, int n_in,
                              void* d_out, int out_size) {
    const float* x        = (const float*)d_in[0];
    const int*   ei       = (const int*)d_in[1];
    const float* gate_w1  = (const float*)d_in[2];
    const float* gate_b1  = (const float*)d_in[3];
    const float* gate_w2  = (const float*)d_in[4];
    const float* gate_b2  = (const float*)d_in[5];
    const float* gcn_w1   = (const float*)d_in[6];
    const float* gcn_b1   = (const float*)d_in[7];
    const float* bn_gamma = (const float*)d_in[8];
    const float* bn_beta  = (const float*)d_in[9];
    const float* gcn_w2   = (const float*)d_in[10];
    const float* gcn_b2   = (const float*)d_in[11];
    const float* gat_w1   = (const float*)d_in[12];
    const float* gat_as1  = (const float*)d_in[13];
    const float* gat_ad1  = (const float*)d_in[14];
    const float* gat_b1   = (const float*)d_in[15];
    const float* gat_w2   = (const float*)d_in[16];
    const float* gat_as2  = (const float*)d_in[17];
    const float* gat_ad2  = (const float*)d_in[18];
    const float* gat_b2   = (const float*)d_in[19];
    const float* sage_wl1 = (const float*)d_in[20];
    const float* sage_bl1 = (const float*)d_in[21];
    const float* sage_wr1 = (const float*)d_in[22];
    const float* sage_wl2 = (const float*)d_in[23];
    const float* sage_bl2 = (const float*)d_in[24];
    const float* sage_wr2 = (const float*)d_in[25];
    float* out = (float*)d_out;

    // Real device address of the scratch symbol (query only; capture-safe).
    float* B = nullptr;
    cudaGetSymbolAddress((void**)&B, g_buf);

    float* gsum   = B + O_GSUM;
    float* gate   = B + O_GATE;
    float* indeg  = B + O_INDEG;
    float* dis    = B + O_DIS;
    float* gcnxh  = B + O_GCNXH;
    float* agg1   = B + O_AGG1;
    float* gcnh1  = B + O_GCNH1;
    float* gcnh2  = B + O_GCNH2;
    float* agg2   = B + O_AGG2;
    float* gath1  = B + O_GATH1;
    float* as1    = B + O_AS1;
    float* ad1    = B + O_AD1;
    float* m1     = B + O_M1;
    float* d1v    = B + O_D1;
    float* gagg1  = B + O_GAGG1;
    float* gath2  = B + O_GATH2;
    float* as2    = B + O_AS2;
    float* ad2    = B + O_AD2;
    float* m2     = B + O_M2;
    float* d2v    = B + O_D2;
    float* gagg2  = B + O_GAGG2;
    float* sxr    = B + O_SXR;
    float* saggx  = B + O_SAGGX;
    float* smean  = B + O_SMEAN;
    float* sml    = B + O_SML;
    float* sh1    = B + O_SH1;
    float* sagg2  = B + O_SAGG2;
    float* smean2 = B + O_SMEAN2;
    float* sml2   = B + O_SML2;
    float* sxr2   = B + O_SXR2;
    float* sout   = B + O_SOUT;

    const int* rowp = ei;
    const int* colp = ei + NE;
    dim3 gb(64, 4);

    zero_all<<<NN, 256>>>(B);
    degree_kernel<<<(NE + 255) / 256, 256>>>(colp, indeg);
    dis_kernel<<<(NN + 255) / 256, 256>>>(indeg, dis);
    colsum_kernel<<<128, 256>>>(x, gsum);
    gate_kernel<<<1, 64>>>(gsum, gate, gate_w1, gate_b1, gate_w2, gate_b2);

    // feature transforms of x
    gemm_kernel<64><<<dim3(NN / 4, 1), gb>>>(x, gcn_w1, gcnxh, NN, 64);
    gemm_kernel<64><<<dim3(NN / 4, 4), gb>>>(x, gat_w1, gath1, NN, 256);
    gemm_kernel<64><<<dim3(NN / 4, 1), gb>>>(x, sage_wr1, sxr, NN, 64);

    // ---- GCN ----
    gcn_edge_agg<<<EP / 4, gb>>>(rowp, colp, dis, gcnxh, agg1);
    gcn_post1<<<(NN * 64 + 255) / 256, 256>>>(agg1, gcnh1, gcn_b1, bn_gamma, bn_beta);
    gemm_kernel<64><<<dim3(NN / 4, 1), gb>>>(gcnh1, gcn_w2, gcnh2, NN, 64);
    gcn_edge_agg<<<EP / 4, gb>>>(rowp, colp, dis, gcnh2, agg2);

    // ---- GAT layer 1 ----
    gat_att1<<<NN, 256>>>(gath1, as1, ad1, gat_as1, gat_ad1);
    gat_max1<<<(EP + 255) / 256, 256>>>(rowp, colp, as1, ad1, m1);
    gat_den1<<<(EP + 255) / 256, 256>>>(rowp, colp, as1, ad1, m1, d1v);
    gat_agg1k<<<EP, 256>>>(rowp, colp, as1, ad1, m1, d1v, gath1, gagg1);
    gat_post1<<<(NN * 256 + 255) / 256, 256>>>(gagg1, gat_b1);
    // ---- GAT layer 2 ----
    gemm_kernel<256><<<dim3(NN / 4, 1), gb>>>(gagg1, gat_w2, gath2, NN, 64);
    gat_att2<<<NN / 4, gb>>>(gath2, as2, ad2, gat_as2, gat_ad2);
    gat_max2<<<(EP + 255) / 256, 256>>>(rowp, colp, as2, ad2, m2);
    gat_den2<<<(EP + 255) / 256, 256>>>(rowp, colp, as2, ad2, m2, d2v);
    gat_agg2k<<<EP / 4, gb>>>(rowp, colp, as2, ad2, m2, d2v, gath2, gagg2);

    // ---- SAGE ----
    sage_edge_agg<<<NE / 4, gb>>>(rowp, colp, x, saggx);
    sage_mean<<<(NN * 64 + 255) / 256, 256>>>(saggx, smean, indeg);
    gemm_kernel<64><<<dim3(NN / 4, 1), gb>>>(smean, sage_wl1, sml, NN, 64);
    sage_post<<<NN / 4, gb>>>(sml, sage_bl1, sxr, sh1, 1);
    sage_edge_agg<<<NE / 4, gb>>>(rowp, colp, sh1, sagg2);
    sage_mean<<<(NN * 64 + 255) / 256, 256>>>(sagg2, smean2, indeg);
    gemm_kernel<64><<<dim3(NN / 4, 1), gb>>>(smean2, sage_wl2, sml2, NN, 64);
    gemm_kernel<64><<<dim3(NN / 4, 1), gb>>>(sh1, sage_wr2, sxr2, NN, 64);
    sage_post<<<NN / 4, gb>>>(sml2, sage_bl2, sxr2, sout, 0);

    // ---- combine ----
    combine_kernel<<<(NN * 64 + 255) / 256, 256>>>(out, gate, agg2, gagg2, sout,
                                                   gcn_b2, gat_b2);
}

// round 5
// speedup vs baseline: 2.4857x; 2.4857x over previous
#include <cuda_runtime.h>
#include <math.h>

#define NN 50000
#define NE 400000
#define EP (NE + NN)   // edges + virtual self loops

// ---------------- scratch layout (floats) --------------------------------
// zeroed-by-memset region first:
#define O_AGG1   0LL
#define O_AGG2   (O_AGG1  + (long long)NN*64)
#define O_GAGG1  (O_AGG2  + (long long)NN*64)
#define O_GAGG2  (O_GAGG1 + (long long)NN*256)
#define O_SAGGX  (O_GAGG2 + (long long)NN*64)
#define O_SAGG2  (O_SAGGX + (long long)NN*64)
#define O_D1     (O_SAGG2 + (long long)NN*64)
#define O_D2     (O_D1    + (long long)NN*4)
#define O_INDEG  (O_D2    + NN)
#define O_GSUM   (O_INDEG + NN)
#define ZEND     (O_GSUM  + 64)
// not zeroed:
#define O_GATE   (ZEND)
#define O_DIS    (O_GATE  + 4)
#define O_GCNXH  (O_DIS   + NN)
#define O_GCNH1  (O_GCNXH + (long long)NN*64)
#define O_GCNH2  (O_GCNH1 + (long long)NN*64)
#define O_GATH1  (O_GCNH2 + (long long)NN*64)
#define O_AS1    (O_GATH1 + (long long)NN*256)
#define O_AD1    (O_AS1   + (long long)NN*4)
#define O_EEXP1  (O_AD1   + (long long)NN*4)
#define O_GATH2  (O_EEXP1 + (long long)EP*4)
#define O_AS2    (O_GATH2 + (long long)NN*64)
#define O_AD2    (O_AS2   + NN)
#define O_EEXP2  (O_AD2   + NN)
#define O_SXR    (O_EEXP2 + EP)
#define O_SMEAN  (O_SXR   + (long long)NN*64)
#define O_SML    (O_SMEAN + (long long)NN*64)
#define O_SH1    (O_SML   + (long long)NN*64)
#define O_SMEAN2 (O_SH1   + (long long)NN*64)
#define O_SML2   (O_SMEAN2+ (long long)NN*64)
#define O_SXR2   (O_SML2  + (long long)NN*64)
#define O_SOUT   (O_SXR2  + (long long)NN*64)
#define SZ_TOTAL (O_SOUT  + (long long)NN*64)

__device__ __align__(256) float g_buf[SZ_TOTAL];

// ---------------- helpers ----------------
__device__ __forceinline__ void redAdd4(float* addr, float a, float b, float c, float d) {
    asm volatile("red.global.add.v4.f32 [%0], {%1,%2,%3,%4};"
                 :: "l"(addr), "f"(a), "f"(b), "f"(c), "f"(d) : "memory");
}
__device__ __forceinline__ float lrelu(float x) { return x > 0.f ? x : 0.2f * x; }

// ---------------- degree / dis ----------------
__global__ void degree_kernel(const int* __restrict__ col, float* __restrict__ indeg) {
    int e = blockIdx.x * blockDim.x + threadIdx.x;
    if (e < NE) atomicAdd(&indeg[col[e]], 1.f);
}
__global__ void dis_kernel(const float* __restrict__ indeg, float* __restrict__ dis) {
    int i = blockIdx.x * blockDim.x + threadIdx.x;
    if (i < NN) dis[i] = rsqrtf(indeg[i] + 1.f);
}

// ---------------- gate ----------------
__global__ void colsum_kernel(const float* __restrict__ x, float* __restrict__ gsum) {
    __shared__ float4 s[256];
    int t = threadIdx.x;
    int c4 = t & 15, rg = t >> 4;
    float4 acc = {0.f, 0.f, 0.f, 0.f};
    for (int i = blockIdx.x * 16 + rg; i < NN; i += gridDim.x * 16) {
        float4 v = ((const float4*)x)[i * 16 + c4];
        acc.x += v.x; acc.y += v.y; acc.z += v.z; acc.w += v.w;
    }
    s[t] = acc;
    __syncthreads();
    for (int st = 128; st >= 16; st >>= 1) {
        if (t < st) {
            s[t].x += s[t + st].x; s[t].y += s[t + st].y;
            s[t].z += s[t + st].z; s[t].w += s[t + st].w;
        }
        __syncthreads();
    }
    if (t < 16) {
        float4 v = s[t];
        atomicAdd(&gsum[t * 4 + 0], v.x);
        atomicAdd(&gsum[t * 4 + 1], v.y);
        atomicAdd(&gsum[t * 4 + 2], v.z);
        atomicAdd(&gsum[t * 4 + 3], v.w);
    }
}

__global__ void gate_kernel(const float* __restrict__ gsum, float* __restrict__ gate,
                            const float* __restrict__ w1, const float* __restrict__ b1,
                            const float* __restrict__ w2, const float* __restrict__ b2) {
    __shared__ float gm[64], hid[64], o[3];
    int t = threadIdx.x;
    gm[t] = gsum[t] / (float)NN;
    __syncthreads();
    float a = b1[t];
    for (int k = 0; k < 64; k++) a += gm[k] * w1[k * 64 + t];
    hid[t] = fmaxf(a, 0.f);
    __syncthreads();
    if (t < 3) {
        float s = b2[t];
        for (int k = 0; k < 64; k++) s += hid[k] * w2[k * 3 + t];
        o[t] = s;
    }
    __syncthreads();
    if (t == 0) {
        float mx = fmaxf(o[0], fmaxf(o[1], o[2]));
        float e0 = expf(o[0] - mx), e1 = expf(o[1] - mx), e2 = expf(o[2] - mx);
        float s = e0 + e1 + e2;
        gate[0] = e0 / s; gate[1] = e1 / s; gate[2] = e2 / s;
    }
}

// ---------------- tiled GEMM: C[n,dout] = A[n,din] @ W[din,dout] ----------
// block 256 thr, tile 32 rows x 64 cols, k chunks of 64
__global__ void gemm_tile(const float* __restrict__ A, const float* __restrict__ W,
                          float* __restrict__ C, int n, int din, int dout) {
    __shared__ float sW[64 * 64];
    __shared__ float sA[32 * 64];
    int t = threadIdx.x;
    int colq = t & 15;       // float4 column group (16 * 4 = 64 cols)
    int rp = t >> 4;         // 0..15 row pair
    int r0 = blockIdx.x * 32;
    int cb = blockIdx.y * 64;
    float4 acc0 = {0.f,0.f,0.f,0.f}, acc1 = {0.f,0.f,0.f,0.f};
    for (int k0 = 0; k0 < din; k0 += 64) {
        for (int i = t; i < 64 * 16; i += 256) {
            int kk = i >> 4, cc = i & 15;
            ((float4*)sW)[i] = ((const float4*)(W + (long long)(k0 + kk) * dout + cb))[cc];
        }
        for (int i = t; i < 32 * 16; i += 256) {
            int rr = i >> 4, kk = i & 15;
            float4 v = {0.f,0.f,0.f,0.f};
            if (r0 + rr < n) v = ((const float4*)(A + (long long)(r0 + rr) * din + k0))[kk];
            ((float4*)sA)[i] = v;
        }
        __syncthreads();
#pragma unroll 16
        for (int k = 0; k < 64; k++) {
            float4 w4 = ((float4*)sW)[k * 16 + colq];
            float a0 = sA[(rp * 2) * 64 + k];
            float a1 = sA[(rp * 2 + 1) * 64 + k];
            acc0.x += a0 * w4.x; acc0.y += a0 * w4.y; acc0.z += a0 * w4.z; acc0.w += a0 * w4.w;
            acc1.x += a1 * w4.x; acc1.y += a1 * w4.y; acc1.z += a1 * w4.z; acc1.w += a1 * w4.w;
        }
        __syncthreads();
    }
    int row = r0 + rp * 2;
    if (row < n)     ((float4*)(C + (long long)row * dout + cb))[colq] = acc0;
    if (row + 1 < n) ((float4*)(C + (long long)(row + 1) * dout + cb))[colq] = acc1;
}

// ---------------- GCN edge aggregate (16 thr/edge, float4) ----------------
__global__ void gcn_edge_agg(const int* __restrict__ row, const int* __restrict__ col,
                             const float* __restrict__ dis,
                             const float* __restrict__ h, float* __restrict__ agg) {
    int t = threadIdx.x;
    int j = t & 15, le = t >> 4;
    int e = blockIdx.x * 16 + le;
    int r, c;
    if (e < NE) { r = row[e]; c = col[e]; } else { r = c = e - NE; }
    float nrm = dis[r] * dis[c];
    float4 v = ((const float4*)h)[r * 16 + j];
    redAdd4(agg + (long long)c * 64 + j * 4, v.x * nrm, v.y * nrm, v.z * nrm, v.w * nrm);
}

__global__ void gcn_post1(const float4* __restrict__ agg1, float4* __restrict__ h1,
                          const float4* __restrict__ b, const float4* __restrict__ gamma,
                          const float4* __restrict__ beta) {
    int i = blockIdx.x * 256 + threadIdx.x;   // NN*16 float4
    if (i >= NN * 16) return;
    int f = i & 15;
    float4 g = gamma[f], bb = b[f], bt = beta[f], a = agg1[i];
    float sc = rsqrtf(1.f + 1e-5f);
    float4 o;
    o.x = fmaxf((a.x + bb.x) * g.x * sc + bt.x, 0.f);
    o.y = fmaxf((a.y + bb.y) * g.y * sc + bt.y, 0.f);
    o.z = fmaxf((a.z + bb.z) * g.z * sc + bt.z, 0.f);
    o.w = fmaxf((a.w + bb.w) * g.w * sc + bt.w, 0.f);
    h1[i] = o;
}

// ---------------- GAT layer 1 ----------------
// warp per node: 256 feats, 4 heads
__global__ void gat_att1(const float* __restrict__ gath1,
                         float* __restrict__ as1, float* __restrict__ ad1,
                         const float* __restrict__ asrc, const float* __restrict__ adst) {
    int t = threadIdx.x;
    int w = t >> 5, l = t & 31;
    int n = blockIdx.x * 8 + w;
    const float4* g4 = (const float4*)(gath1 + (long long)n * 256);
    float4 a = g4[l * 2], b = g4[l * 2 + 1];
    int h = l >> 3;
    int off = (l & 7) * 8;
    const float* As = asrc + h * 64 + off;
    const float* Ad = adst + h * 64 + off;
    float ss = a.x*As[0] + a.y*As[1] + a.z*As[2] + a.w*As[3]
             + b.x*As[4] + b.y*As[5] + b.z*As[6] + b.w*As[7];
    float sd = a.x*Ad[0] + a.y*Ad[1] + a.z*Ad[2] + a.w*Ad[3]
             + b.x*Ad[4] + b.y*Ad[5] + b.z*Ad[6] + b.w*Ad[7];
    ss += __shfl_xor_sync(0xffffffffu, ss, 1);
    sd += __shfl_xor_sync(0xffffffffu, sd, 1);
    ss += __shfl_xor_sync(0xffffffffu, ss, 2);
    sd += __shfl_xor_sync(0xffffffffu, sd, 2);
    ss += __shfl_xor_sync(0xffffffffu, ss, 4);
    sd += __shfl_xor_sync(0xffffffffu, sd, 4);
    if ((l & 7) == 0) { as1[n * 4 + h] = ss; ad1[n * 4 + h] = sd; }
}

// no max-subtraction needed (logits are O(1)); exp(e)/sum(exp(e)) is exact softmax
__global__ void gat_den1(const int* __restrict__ row, const int* __restrict__ col,
                         const float* __restrict__ as1, const float* __restrict__ ad1,
                         float* __restrict__ d1, float* __restrict__ eexp1) {
    int e = blockIdx.x * blockDim.x + threadIdx.x;
    if (e >= EP) return;
    int r, c;
    if (e < NE) { r = row[e]; c = col[e]; } else { r = c = e - NE; }
    float4 s = ((const float4*)as1)[r];
    float4 d = ((const float4*)ad1)[c];
    float e0 = __expf(lrelu(s.x + d.x));
    float e1 = __expf(lrelu(s.y + d.y));
    float e2 = __expf(lrelu(s.z + d.z));
    float e3 = __expf(lrelu(s.w + d.w));
    float4 o = {e0, e1, e2, e3};
    ((float4*)eexp1)[e] = o;
    redAdd4(d1 + (long long)c * 4, e0, e1, e2, e3);
}

// 64 thr/edge (float4 over 256 feats), 4 edges/block
__global__ void gat_agg1(const int* __restrict__ row, const int* __restrict__ col,
                         const float* __restrict__ eexp1, const float* __restrict__ d1,
                         const float* __restrict__ gath1, float* __restrict__ gagg1) {
    int t = threadIdx.x;
    int j = t & 63, le = t >> 6;
    int e = blockIdx.x * 4 + le;
    int r, c;
    if (e < NE) { r = row[e]; c = col[e]; } else { r = c = e - NE; }
    int h = j >> 4;
    float alpha = eexp1[e * 4 + h] / d1[c * 4 + h];
    float4 v = ((const float4*)gath1)[(long long)r * 64 + j];
    redAdd4(gagg1 + (long long)c * 256 + j * 4,
            v.x * alpha, v.y * alpha, v.z * alpha, v.w * alpha);
}

__global__ void gat_post1(float4* __restrict__ gagg1, const float4* __restrict__ b) {
    long long i = (long long)blockIdx.x * 256 + threadIdx.x;  // NN*64 float4
    if (i >= (long long)NN * 64) return;
    float4 bb = b[i & 63];
    float4 v = gagg1[i];
    v.x += bb.x; v.y += bb.y; v.z += bb.z; v.w += bb.w;
    v.x = v.x > 0.f ? v.x : (expf(v.x) - 1.f);
    v.y = v.y > 0.f ? v.y : (expf(v.y) - 1.f);
    v.z = v.z > 0.f ? v.z : (expf(v.z) - 1.f);
    v.w = v.w > 0.f ? v.w : (expf(v.w) - 1.f);
    gagg1[i] = v;
}

// ---------------- GAT layer 2 ----------------
__global__ void gat_att2(const float* __restrict__ gath2,
                         float* __restrict__ as2, float* __restrict__ ad2,
                         const float* __restrict__ asrc, const float* __restrict__ adst) {
    int t = threadIdx.x;
    int w = t >> 5, l = t & 31;
    int n = blockIdx.x * 8 + w;
    float v0 = gath2[n * 64 + l], v1 = gath2[n * 64 + 32 + l];
    float ss = v0 * asrc[l] + v1 * asrc[32 + l];
    float sd = v0 * adst[l] + v1 * adst[32 + l];
    for (int o = 16; o > 0; o >>= 1) {
        ss += __shfl_xor_sync(0xffffffffu, ss, o);
        sd += __shfl_xor_sync(0xffffffffu, sd, o);
    }
    if (l == 0) { as2[n] = ss; ad2[n] = sd; }
}

__global__ void gat_den2(const int* __restrict__ row, const int* __restrict__ col,
                         const float* __restrict__ as2, const float* __restrict__ ad2,
                         float* __restrict__ d2, float* __restrict__ eexp2) {
    int e = blockIdx.x * blockDim.x + threadIdx.x;
    if (e >= EP) return;
    int r, c;
    if (e < NE) { r = row[e]; c = col[e]; } else { r = c = e - NE; }
    float x = __expf(lrelu(as2[r] + ad2[c]));
    eexp2[e] = x;
    atomicAdd(&d2[c], x);
}

__global__ void gat_agg2(const int* __restrict__ row, const int* __restrict__ col,
                         const float* __restrict__ eexp2, const float* __restrict__ d2,
                         const float* __restrict__ gath2, float* __restrict__ gagg2) {
    int t = threadIdx.x;
    int j = t & 15, le = t >> 4;
    int e = blockIdx.x * 16 + le;
    int r, c;
    if (e < NE) { r = row[e]; c = col[e]; } else { r = c = e - NE; }
    float alpha = eexp2[e] / d2[c];
    float4 v = ((const float4*)gath2)[r * 16 + j];
    redAdd4(gagg2 + (long long)c * 64 + j * 4,
            v.x * alpha, v.y * alpha, v.z * alpha, v.w * alpha);
}

// ---------------- SAGE ----------------
__global__ void sage_edge_agg(const int* __restrict__ row, const int* __restrict__ col,
                              const float* __restrict__ h, float* __restrict__ agg) {
    int t = threadIdx.x;
    int j = t & 15, le = t >> 4;
    int e = blockIdx.x * 16 + le;
    int r = row[e], c = col[e];
    float4 v = ((const float4*)h)[r * 16 + j];
    redAdd4(agg + (long long)c * 64 + j * 4, v.x, v.y, v.z, v.w);
}

__global__ void sage_mean(const float4* __restrict__ src, float4* __restrict__ dst,
                          const float* __restrict__ indeg) {
    int i = blockIdx.x * 256 + threadIdx.x;   // NN*16 float4
    if (i >= NN * 16) return;
    float inv = 1.f / fmaxf(indeg[i >> 4], 1.f);
    float4 v = src[i];
    v.x *= inv; v.y *= inv; v.z *= inv; v.w *= inv;
    dst[i] = v;
}

// warp per row L2-normalize
__global__ void sage_post(const float* __restrict__ ml, const float* __restrict__ bl,
                          const float* __restrict__ xr, float* __restrict__ out, int dorelu) {
    int t = threadIdx.x;
    int w = t >> 5, l = t & 31;
    int n = blockIdx.x * 8 + w;
    float v0 = ml[n * 64 + l] + bl[l] + xr[n * 64 + l];
    float v1 = ml[n * 64 + 32 + l] + bl[32 + l] + xr[n * 64 + 32 + l];
    float ss = v0 * v0 + v1 * v1;
    for (int o = 16; o > 0; o >>= 1) ss += __shfl_xor_sync(0xffffffffu, ss, o);
    float inv = 1.f / fmaxf(sqrtf(ss), 1e-12f);
    float o0 = v0 * inv, o1 = v1 * inv;
    if (dorelu) { o0 = fmaxf(o0, 0.f); o1 = fmaxf(o1, 0.f); }
    out[n * 64 + l] = o0;
    out[n * 64 + 32 + l] = o1;
}

// ---------------- final combine ----------------
__global__ void combine_kernel(float4* __restrict__ out, const float* __restrict__ gate,
                               const float4* __restrict__ agg2, const float4* __restrict__ gagg2,
                               const float4* __restrict__ sout,
                               const float4* __restrict__ gcn_b2, const float4* __restrict__ gat_b2) {
    int i = blockIdx.x * 256 + threadIdx.x;   // NN*16 float4
    if (i >= NN * 16) return;
    int f = i & 15;
    float w0 = gate[0], w1 = gate[1], w2 = gate[2];
    float4 b0 = gcn_b2[f], b1 = gat_b2[f];
    float4 a = agg2[i], g = gagg2[i], s = sout[i];
    float4 o;
    o.x = w0 * (a.x + b0.x) + w1 * (g.x + b1.x) + w2 * s.x;
    o.y = w0 * (a.y + b0.y) + w1 * (g.y + b1.y) + w2 * s.y;
    o.z = w0 * (a.z + b0.z) + w1 * (g.z + b1.z) + w2 * s.z;
    o.w = w0 * (a.w + b0.w) + w1 * (g.w + b1.w) + w2 * s.w;
    out[i] = o;
}

// ---------------- launch ----------------
extern "C" void kernel_launch(void* const* d_in, const int* in_sizes, int n_in,
                              void* d_out, int out_size) {
    const float* x        = (const float*)d_in[0];
    const int*   ei       = (const int*)d_in[1];
    const float* gate_w1  = (const float*)d_in[2];
    const float* gate_b1  = (const float*)d_in[3];
    const float* gate_w2  = (const float*)d_in[4];
    const float* gate_b2  = (const float*)d_in[5];
    const float* gcn_w1   = (const float*)d_in[6];
    const float* gcn_b1   = (const float*)d_in[7];
    const float* bn_gamma = (const float*)d_in[8];
    const float* bn_beta  = (const float*)d_in[9];
    const float* gcn_w2   = (const float*)d_in[10];
    const float* gcn_b2   = (const float*)d_in[11];
    const float* gat_w1   = (const float*)d_in[12];
    const float* gat_as1  = (const float*)d_in[13];
    const float* gat_ad1  = (const float*)d_in[14];
    const float* gat_b1   = (const float*)d_in[15];
    const float* gat_w2   = (const float*)d_in[16];
    const float* gat_as2  = (const float*)d_in[17];
    const float* gat_ad2  = (const float*)d_in[18];
    const float* gat_b2   = (const float*)d_in[19];
    const float* sage_wl1 = (const float*)d_in[20];
    const float* sage_bl1 = (const float*)d_in[21];
    const float* sage_wr1 = (const float*)d_in[22];
    const float* sage_wl2 = (const float*)d_in[23];
    const float* sage_bl2 = (const float*)d_in[24];
    const float* sage_wr2 = (const float*)d_in[25];
    float* out = (float*)d_out;

    float* B = nullptr;
    cudaGetSymbolAddress((void**)&B, g_buf);

    float* agg1   = B + O_AGG1;
    float* agg2   = B + O_AGG2;
    float* gagg1  = B + O_GAGG1;
    float* gagg2  = B + O_GAGG2;
    float* saggx  = B + O_SAGGX;
    float* sagg2  = B + O_SAGG2;
    float* d1v    = B + O_D1;
    float* d2v    = B + O_D2;
    float* indeg  = B + O_INDEG;
    float* gsum   = B + O_GSUM;
    float* gate   = B + O_GATE;
    float* dis    = B + O_DIS;
    float* gcnxh  = B + O_GCNXH;
    float* gcnh1  = B + O_GCNH1;
    float* gcnh2  = B + O_GCNH2;
    float* gath1  = B + O_GATH1;
    float* as1    = B + O_AS1;
    float* ad1    = B + O_AD1;
    float* eexp1  = B + O_EEXP1;
    float* gath2  = B + O_GATH2;
    float* as2    = B + O_AS2;
    float* ad2    = B + O_AD2;
    float* eexp2  = B + O_EEXP2;
    float* sxr    = B + O_SXR;
    float* smean  = B + O_SMEAN;
    float* sml    = B + O_SML;
    float* sh1    = B + O_SH1;
    float* smean2 = B + O_SMEAN2;
    float* sml2   = B + O_SML2;
    float* sxr2   = B + O_SXR2;
    float* sout   = B + O_SOUT;

    const int* rowp = ei;
    const int* colp = ei + NE;

    // zero all accumulators in one memset (contiguous region)
    cudaMemsetAsync(B, 0, (size_t)ZEND * sizeof(float), 0);

    degree_kernel<<<(NE + 255) / 256, 256>>>(colp, indeg);
    dis_kernel<<<(NN + 255) / 256, 256>>>(indeg, dis);
    colsum_kernel<<<512, 256>>>(x, gsum);
    gate_kernel<<<1, 64>>>(gsum, gate, gate_w1, gate_b1, gate_w2, gate_b2);

    const int GB = (NN + 31) / 32;   // gemm row-tiles
    // feature transforms of x
    gemm_tile<<<dim3(GB, 1), 256>>>(x, gcn_w1, gcnxh, NN, 64, 64);
    gemm_tile<<<dim3(GB, 4), 256>>>(x, gat_w1, gath1, NN, 64, 256);
    gemm_tile<<<dim3(GB, 1), 256>>>(x, sage_wr1, sxr, NN, 64, 64);

    // ---- GCN ----
    gcn_edge_agg<<<EP / 16, 256>>>(rowp, colp, dis, gcnxh, agg1);
    gcn_post1<<<(NN * 16 + 255) / 256, 256>>>((const float4*)agg1, (float4*)gcnh1,
                                              (const float4*)gcn_b1, (const float4*)bn_gamma,
                                              (const float4*)bn_beta);
    gemm_tile<<<dim3(GB, 1), 256>>>(gcnh1, gcn_w2, gcnh2, NN, 64, 64);
    gcn_edge_agg<<<EP / 16, 256>>>(rowp, colp, dis, gcnh2, agg2);

    // ---- GAT layer 1 ----
    gat_att1<<<NN / 8, 256>>>(gath1, as1, ad1, gat_as1, gat_ad1);
    gat_den1<<<(EP + 255) / 256, 256>>>(rowp, colp, as1, ad1, d1v, eexp1);
    gat_agg1<<<EP / 4, 256>>>(rowp, colp, eexp1, d1v, gath1, gagg1);
    gat_post1<<<(NN * 64 + 255) / 256, 256>>>((float4*)gagg1, (const float4*)gat_b1);

    // ---- GAT layer 2 ----
    gemm_tile<<<dim3(GB, 1), 256>>>(gagg1, gat_w2, gath2, NN, 256, 64);
    gat_att2<<<NN / 8, 256>>>(gath2, as2, ad2, gat_as2, gat_ad2);
    gat_den2<<<(EP + 255) / 256, 256>>>(rowp, colp, as2, ad2, d2v, eexp2);
    gat_agg2<<<EP / 16, 256>>>(rowp, colp, eexp2, d2v, gath2, gagg2);

    // ---- SAGE ----
    sage_edge_agg<<<NE / 16, 256>>>(rowp, colp, x, saggx);
    sage_mean<<<(NN * 16 + 255) / 256, 256>>>((const float4*)saggx, (float4*)smean, indeg);
    gemm_tile<<<dim3(GB, 1), 256>>>(smean, sage_wl1, sml, NN, 64, 64);
    sage_post<<<NN / 8, 256>>>(sml, sage_bl1, sxr, sh1, 1);
    sage_edge_agg<<<NE / 16, 256>>>(rowp, colp, sh1, sagg2);
    sage_mean<<<(NN * 16 + 255) / 256, 256>>>((const float4*)sagg2, (float4*)smean2, indeg);
    gemm_tile<<<dim3(GB, 1), 256>>>(smean2, sage_wl2, sml2, NN, 64, 64);
    gemm_tile<<<dim3(GB, 1), 256>>>(sh1, sage_wr2, sxr2, NN, 64, 64);
    sage_post<<<NN / 8, 256>>>(sml2, sage_bl2, sxr2, sout, 0);

    // ---- combine ----
    combine_kernel<<<(NN * 16 + 255) / 256, 256>>>((float4*)out, gate,
                                                   (const float4*)agg2, (const float4*)gagg2,
                                                   (const float4*)sout,
                                                   (const float4*)gcn_b2, (const float4*)gat_b2);
}

// round 7
// speedup vs baseline: 3.8731x; 1.5582x over previous
#include <cuda_runtime.h>
#include <math.h>

#define NN 50000
#define NE 400000
#define NB 196   // ceil(NN/256) scan blocks

// ---------------- scratch layout (float/int aliased units of 4B) ----------
#define O_ECNT   0LL                      // int[NN]  (zeroed by memset)
#define O_GSUM   (O_ECNT + NN)            // float[64] (zeroed)
#define ZEND     (O_GSUM + 64)
#define O_GATE   (ZEND)
#define O_DIS    (O_GATE + 4)
#define O_OFF    (O_DIS  + NN)            // int[NN+1]
#define O_CUR    (O_OFF  + NN + 8)        // int[NN]
#define O_SRC    (O_CUR  + NN)            // int[NE]
#define O_BSUM   (O_SRC  + NE)            // int[256]
#define O_BOFF   (O_BSUM + 256)           // int[256]
#define O_GCNXH  (O_BOFF + 256)
#define O_GCNH1  (O_GCNXH + (long long)NN*64)
#define O_GCNH2  (O_GCNH1 + (long long)NN*64)
#define O_AGG2   (O_GCNH2 + (long long)NN*64)
#define O_GATH1  (O_AGG2  + (long long)NN*64)
#define O_AS1    (O_GATH1 + (long long)NN*256)
#define O_AD1    (O_AS1   + (long long)NN*4)
#define O_GAGG1  (O_AD1   + (long long)NN*4)
#define O_GATH2  (O_GAGG1 + (long long)NN*256)
#define O_AS2    (O_GATH2 + (long long)NN*64)
#define O_AD2    (O_AS2   + NN)
#define O_GAGG2  (O_AD2   + NN)
#define O_SXR    (O_GAGG2 + (long long)NN*64)
#define O_SMEAN  (O_SXR   + (long long)NN*64)
#define O_SML    (O_SMEAN + (long long)NN*64)
#define O_SH1    (O_SML   + (long long)NN*64)
#define O_SMEAN2 (O_SH1   + (long long)NN*64)
#define O_SML2   (O_SMEAN2+ (long long)NN*64)
#define O_SXR2   (O_SML2  + (long long)NN*64)
#define O_SOUT   (O_SXR2  + (long long)NN*64)
#define SZ_TOTAL (O_SOUT  + (long long)NN*64)

__device__ __align__(256) float g_buf[SZ_TOTAL];

__device__ __forceinline__ float lrelu(float x) { return x > 0.f ? x : 0.2f * x; }

// ================= CSR build =================
__global__ void degree_kernel(const int* __restrict__ col, int* __restrict__ ecnt) {
    int e = blockIdx.x * blockDim.x + threadIdx.x;
    if (e < NE) atomicAdd(&ecnt[col[e]], 1);
}

__global__ void scan_bsum(const int* __restrict__ ecnt, int* __restrict__ bsum) {
    __shared__ int s[256];
    int i = blockIdx.x * 256 + threadIdx.x;
    s[threadIdx.x] = (i < NN) ? ecnt[i] : 0;
    __syncthreads();
    for (int o = 128; o > 0; o >>= 1) {
        if (threadIdx.x < o) s[threadIdx.x] += s[threadIdx.x + o];
        __syncthreads();
    }
    if (threadIdx.x == 0) bsum[blockIdx.x] = s[0];
}

__global__ void scan_boff(const int* __restrict__ bsum, int* __restrict__ boff) {
    __shared__ int s[256];
    int t = threadIdx.x;
    int v = (t < NB) ? bsum[t] : 0;
    s[t] = v;
    __syncthreads();
    for (int o = 1; o < 256; o <<= 1) {
        int x = (t >= o) ? s[t - o] : 0;
        __syncthreads();
        s[t] += x;
        __syncthreads();
    }
    boff[t] = s[t] - v;   // exclusive
}

__global__ void scan_final(const int* __restrict__ ecnt, const int* __restrict__ boff,
                           int* __restrict__ off, int* __restrict__ cursor) {
    __shared__ int s[256];
    int t = threadIdx.x;
    int i = blockIdx.x * 256 + t;
    int v = (i < NN) ? ecnt[i] : 0;
    s[t] = v;
    __syncthreads();
    for (int o = 1; o < 256; o <<= 1) {
        int x = (t >= o) ? s[t - o] : 0;
        __syncthreads();
        s[t] += x;
        __syncthreads();
    }
    if (i < NN) { off[i] = boff[blockIdx.x] + s[t] - v; cursor[i] = 0; }
    if (i == 0) off[NN] = NE;
}

__global__ void scatter_kernel(const int* __restrict__ row, const int* __restrict__ col,
                               const int* __restrict__ off, int* __restrict__ cursor,
                               int* __restrict__ srcv) {
    int e = blockIdx.x * 256 + threadIdx.x;
    if (e >= NE) return;
    int c = col[e];
    int p = off[c] + atomicAdd(&cursor[c], 1);
    srcv[p] = row[e];
}

__global__ void dis_kernel(const int* __restrict__ off, float* __restrict__ dis) {
    int i = blockIdx.x * blockDim.x + threadIdx.x;
    if (i < NN) dis[i] = rsqrtf((float)(off[i + 1] - off[i]) + 1.f);
}

// ================= gate =================
__global__ void colsum_kernel(const float* __restrict__ x, float* __restrict__ gsum) {
    __shared__ float4 s[256];
    int t = threadIdx.x;
    int c4 = t & 15, rg = t >> 4;
    float4 acc = {0.f, 0.f, 0.f, 0.f};
    for (int i = blockIdx.x * 16 + rg; i < NN; i += gridDim.x * 16) {
        float4 v = ((const float4*)x)[i * 16 + c4];
        acc.x += v.x; acc.y += v.y; acc.z += v.z; acc.w += v.w;
    }
    s[t] = acc;
    __syncthreads();
    for (int st = 128; st >= 16; st >>= 1) {
        if (t < st) {
            s[t].x += s[t + st].x; s[t].y += s[t + st].y;
            s[t].z += s[t + st].z; s[t].w += s[t + st].w;
        }
        __syncthreads();
    }
    if (t < 16) {
        float4 v = s[t];
        atomicAdd(&gsum[t * 4 + 0], v.x);
        atomicAdd(&gsum[t * 4 + 1], v.y);
        atomicAdd(&gsum[t * 4 + 2], v.z);
        atomicAdd(&gsum[t * 4 + 3], v.w);
    }
}

__global__ void gate_kernel(const float* __restrict__ gsum, float* __restrict__ gate,
                            const float* __restrict__ w1, const float* __restrict__ b1,
                            const float* __restrict__ w2, const float* __restrict__ b2) {
    __shared__ float gm[64], hid[64], o[3];
    int t = threadIdx.x;
    gm[t] = gsum[t] / (float)NN;
    __syncthreads();
    float a = b1[t];
    for (int k = 0; k < 64; k++) a += gm[k] * w1[k * 64 + t];
    hid[t] = fmaxf(a, 0.f);
    __syncthreads();
    if (t < 3) {
        float s = b2[t];
        for (int k = 0; k < 64; k++) s += hid[k] * w2[k * 3 + t];
        o[t] = s;
    }
    __syncthreads();
    if (t == 0) {
        float mx = fmaxf(o[0], fmaxf(o[1], o[2]));
        float e0 = expf(o[0] - mx), e1 = expf(o[1] - mx), e2 = expf(o[2] - mx);
        float s = e0 + e1 + e2;
        gate[0] = e0 / s; gate[1] = e1 / s; gate[2] = e2 / s;
    }
}

// ================= GEMM: 64x64 tile, 256 thr, 4 rows/thread =================
__global__ void gemm_tile(const float* __restrict__ A, const float* __restrict__ W,
                          float* __restrict__ C, int n, int din, int dout) {
    __shared__ float sW[64 * 64];
    __shared__ float sA[64 * 64];
    int t = threadIdx.x;
    int colq = t & 15;       // float4 col group
    int rq = t >> 4;         // 0..15 -> rows rq*4..rq*4+3
    int r0 = blockIdx.x * 64;
    int cb = blockIdx.y * 64;
    float4 acc[4];
#pragma unroll
    for (int i = 0; i < 4; i++) acc[i] = make_float4(0.f, 0.f, 0.f, 0.f);
    for (int k0 = 0; k0 < din; k0 += 64) {
#pragma unroll
        for (int u = 0; u < 4; u++) {
            int i = t + u * 256;           // 0..1023 float4 slots
            int kk = i >> 4, cc = i & 15;
            ((float4*)sW)[i] = ((const float4*)(W + (long long)(k0 + kk) * dout + cb))[cc];
            int rr = i >> 4;
            float4 v = make_float4(0.f, 0.f, 0.f, 0.f);
            if (r0 + rr < n) v = ((const float4*)(A + (long long)(r0 + rr) * din + k0))[cc];
            ((float4*)sA)[i] = v;
        }
        __syncthreads();
#pragma unroll 8
        for (int k = 0; k < 64; k++) {
            float4 w4 = ((float4*)sW)[k * 16 + colq];
#pragma unroll
            for (int i = 0; i < 4; i++) {
                float a = sA[(rq * 4 + i) * 64 + k];
                acc[i].x += a * w4.x; acc[i].y += a * w4.y;
                acc[i].z += a * w4.z; acc[i].w += a * w4.w;
            }
        }
        __syncthreads();
    }
#pragma unroll
    for (int i = 0; i < 4; i++) {
        int row = r0 + rq * 4 + i;
        if (row < n) ((float4*)(C + (long long)row * dout + cb))[colq] = acc[i];
    }
}

// ================= per-node aggregations (warp per node) =================
// GCN: out[c] = dis[c] * (sum_r dis[r]*h[r] + dis[c]*h[c]); optional BN+ReLU
template <int EPI>
__global__ void gcn_node(const int* __restrict__ off, const int* __restrict__ srcv,
                         const float* __restrict__ dis, const float* __restrict__ h,
                         float* __restrict__ out, const float* __restrict__ b,
                         const float* __restrict__ gamma, const float* __restrict__ beta) {
    int w = (blockIdx.x * blockDim.x + threadIdx.x) >> 5;
    int l = threadIdx.x & 31;
    if (w >= NN) return;
    int beg = off[w], end = off[w + 1];
    float dn = dis[w];
    const float2* h2 = (const float2*)h;
    float2 acc = make_float2(0.f, 0.f);
    for (int p = beg; p < end; p++) {
        int s = srcv[p];
        float ds = dis[s];
        float2 v = h2[s * 32 + l];
        acc.x += v.x * ds; acc.y += v.y * ds;
    }
    float2 hs = h2[w * 32 + l];
    acc.x = (acc.x + dn * hs.x) * dn;
    acc.y = (acc.y + dn * hs.y) * dn;
    if (EPI) {
        float sc = rsqrtf(1.f + 1e-5f);
        float b0 = b[l * 2], b1 = b[l * 2 + 1];
        float g0 = gamma[l * 2] * sc, g1 = gamma[l * 2 + 1] * sc;
        float t0 = beta[l * 2], t1 = beta[l * 2 + 1];
        acc.x = fmaxf((acc.x + b0) * g0 + t0, 0.f);
        acc.y = fmaxf((acc.y + b1) * g1 + t1, 0.f);
    }
    ((float2*)out)[w * 32 + l] = acc;
}

// GAT attention coefficients, layer 1 (4 heads, 256 feats) — warp per node
__global__ void gat_att1(const float* __restrict__ gath1,
                         float* __restrict__ as1, float* __restrict__ ad1,
                         const float* __restrict__ asrc, const float* __restrict__ adst) {
    int t = threadIdx.x;
    int w = t >> 5, l = t & 31;
    int n = blockIdx.x * 8 + w;
    const float4* g4 = (const float4*)(gath1 + (long long)n * 256);
    float4 a = g4[l * 2], b = g4[l * 2 + 1];
    int h = l >> 3;
    int offv = (l & 7) * 8;
    const float* As = asrc + h * 64 + offv;
    const float* Ad = adst + h * 64 + offv;
    float ss = a.x*As[0] + a.y*As[1] + a.z*As[2] + a.w*As[3]
             + b.x*As[4] + b.y*As[5] + b.z*As[6] + b.w*As[7];
    float sd = a.x*Ad[0] + a.y*Ad[1] + a.z*Ad[2] + a.w*Ad[3]
             + b.x*Ad[4] + b.y*Ad[5] + b.z*Ad[6] + b.w*Ad[7];
    ss += __shfl_xor_sync(0xffffffffu, ss, 1);
    sd += __shfl_xor_sync(0xffffffffu, sd, 1);
    ss += __shfl_xor_sync(0xffffffffu, ss, 2);
    sd += __shfl_xor_sync(0xffffffffu, sd, 2);
    ss += __shfl_xor_sync(0xffffffffu, ss, 4);
    sd += __shfl_xor_sync(0xffffffffu, sd, 4);
    if ((l & 7) == 0) { as1[n * 4 + h] = ss; ad1[n * 4 + h] = sd; }
}

__device__ __forceinline__ float4 exp_lrelu4(float4 s, float4 d) {
    float4 o;
    o.x = __expf(lrelu(s.x + d.x));
    o.y = __expf(lrelu(s.y + d.y));
    o.z = __expf(lrelu(s.z + d.z));
    o.w = __expf(lrelu(s.w + d.w));
    return o;
}
__device__ __forceinline__ float sel4(float4 v, int h) {
    float r = v.x;
    r = (h == 1) ? v.y : r;
    r = (h == 2) ? v.z : r;
    r = (h == 3) ? v.w : r;
    return r;
}

// GAT layer-1 fused: denom + aggregate + bias + ELU. Warp per node, 256 feats.
__global__ void gat1_node(const int* __restrict__ off, const int* __restrict__ srcv,
                          const float* __restrict__ as1, const float* __restrict__ ad1,
                          const float* __restrict__ gh, float* __restrict__ out,
                          const float* __restrict__ bias) {
    int w = (blockIdx.x * blockDim.x + threadIdx.x) >> 5;
    int l = threadIdx.x & 31;
    if (w >= NN) return;
    int beg = off[w], end = off[w + 1];
    const float4* as4 = (const float4*)as1;
    float4 adn = ((const float4*)ad1)[w];
    // denominator (lane-parallel over edges)
    float4 ds = make_float4(0.f, 0.f, 0.f, 0.f);
    for (int p = beg + l; p < end; p += 32) {
        float4 e4 = exp_lrelu4(as4[srcv[p]], adn);
        ds.x += e4.x; ds.y += e4.y; ds.z += e4.z; ds.w += e4.w;
    }
#pragma unroll
    for (int o = 16; o > 0; o >>= 1) {
        ds.x += __shfl_xor_sync(0xffffffffu, ds.x, o);
        ds.y += __shfl_xor_sync(0xffffffffu, ds.y, o);
        ds.z += __shfl_xor_sync(0xffffffffu, ds.z, o);
        ds.w += __shfl_xor_sync(0xffffffffu, ds.w, o);
    }
    float4 eself = exp_lrelu4(as4[w], adn);
    ds.x += eself.x; ds.y += eself.y; ds.z += eself.z; ds.w += eself.w;
    int h = l >> 3;                      // this lane's head (8 floats within one head)
    float rden = 1.f / sel4(ds, h);
    float adh = sel4(adn, h);
    // feature aggregation: lane covers floats [l*8, l*8+8)
    float4 a0 = make_float4(0.f, 0.f, 0.f, 0.f), a1 = a0;
    for (int p = beg; p < end; p++) {
        int s = srcv[p];
        float e = __expf(lrelu(sel4(as4[s], h) + adh));
        float alpha = e * rden;
        const float4* gr = (const float4*)(gh + (long long)s * 256) + l * 2;
        float4 v0 = gr[0], v1 = gr[1];
        a0.x += alpha * v0.x; a0.y += alpha * v0.y; a0.z += alpha * v0.z; a0.w += alpha * v0.w;
        a1.x += alpha * v1.x; a1.y += alpha * v1.y; a1.z += alpha * v1.z; a1.w += alpha * v1.w;
    }
    {   // self edge
        float alpha = sel4(eself, h) * rden;
        const float4* gr = (const float4*)(gh + (long long)w * 256) + l * 2;
        float4 v0 = gr[0], v1 = gr[1];
        a0.x += alpha * v0.x; a0.y += alpha * v0.y; a0.z += alpha * v0.z; a0.w += alpha * v0.w;
        a1.x += alpha * v1.x; a1.y += alpha * v1.y; a1.z += alpha * v1.z; a1.w += alpha * v1.w;
    }
    // bias + ELU epilogue
    const float4* b4 = (const float4*)bias + l * 2;
    float4 bb0 = b4[0], bb1 = b4[1];
    a0.x += bb0.x; a0.y += bb0.y; a0.z += bb0.z; a0.w += bb0.w;
    a1.x += bb1.x; a1.y += bb1.y; a1.z += bb1.z; a1.w += bb1.w;
    a0.x = a0.x > 0.f ? a0.x : (expf(a0.x) - 1.f);
    a0.y = a0.y > 0.f ? a0.y : (expf(a0.y) - 1.f);
    a0.z = a0.z > 0.f ? a0.z : (expf(a0.z) - 1.f);
    a0.w = a0.w > 0.f ? a0.w : (expf(a0.w) - 1.f);
    a1.x = a1.x > 0.f ? a1.x : (expf(a1.x) - 1.f);
    a1.y = a1.y > 0.f ? a1.y : (expf(a1.y) - 1.f);
    a1.z = a1.z > 0.f ? a1.z : (expf(a1.z) - 1.f);
    a1.w = a1.w > 0.f ? a1.w : (expf(a1.w) - 1.f);
    float4* o4 = (float4*)(out + (long long)w * 256) + l * 2;
    o4[0] = a0; o4[1] = a1;
}

__global__ void gat_att2(const float* __restrict__ gath2,
                         float* __restrict__ as2, float* __restrict__ ad2,
                         const float* __restrict__ asrc, const float* __restrict__ adst) {
    int t = threadIdx.x;
    int w = t >> 5, l = t & 31;
    int n = blockIdx.x * 8 + w;
    float v0 = gath2[n * 64 + l], v1 = gath2[n * 64 + 32 + l];
    float ss = v0 * asrc[l] + v1 * asrc[32 + l];
    float sd = v0 * adst[l] + v1 * adst[32 + l];
    for (int o = 16; o > 0; o >>= 1) {
        ss += __shfl_xor_sync(0xffffffffu, ss, o);
        sd += __shfl_xor_sync(0xffffffffu, sd, o);
    }
    if (l == 0) { as2[n] = ss; ad2[n] = sd; }
}

// GAT layer-2 fused: denom + aggregate (1 head, 64 feats). Warp per node.
__global__ void gat2_node(const int* __restrict__ off, const int* __restrict__ srcv,
                          const float* __restrict__ as2, const float* __restrict__ ad2,
                          const float* __restrict__ gh, float* __restrict__ out) {
    int w = (blockIdx.x * blockDim.x + threadIdx.x) >> 5;
    int l = threadIdx.x & 31;
    if (w >= NN) return;
    int beg = off[w], end = off[w + 1];
    float adn = ad2[w];
    float ds = 0.f;
    for (int p = beg + l; p < end; p += 32)
        ds += __expf(lrelu(as2[srcv[p]] + adn));
#pragma unroll
    for (int o = 16; o > 0; o >>= 1) ds += __shfl_xor_sync(0xffffffffu, ds, o);
    float eself = __expf(lrelu(as2[w] + adn));
    ds += eself;
    float rden = 1.f / ds;
    const float2* h2 = (const float2*)gh;
    float2 acc = make_float2(0.f, 0.f);
    for (int p = beg; p < end; p++) {
        int s = srcv[p];
        float alpha = __expf(lrelu(as2[s] + adn)) * rden;
        float2 v = h2[s * 32 + l];
        acc.x += alpha * v.x; acc.y += alpha * v.y;
    }
    {
        float alpha = eself * rden;
        float2 v = h2[w * 32 + l];
        acc.x += alpha * v.x; acc.y += alpha * v.y;
    }
    ((float2*)out)[w * 32 + l] = acc;
}

// SAGE mean aggregate (no self loops). Warp per node; writes mean directly.
__global__ void sage_node(const int* __restrict__ off, const int* __restrict__ srcv,
                          const float* __restrict__ h, float* __restrict__ out) {
    int w = (blockIdx.x * blockDim.x + threadIdx.x) >> 5;
    int l = threadIdx.x & 31;
    if (w >= NN) return;
    int beg = off[w], end = off[w + 1];
    const float2* h2 = (const float2*)h;
    float2 acc = make_float2(0.f, 0.f);
    for (int p = beg; p < end; p++) {
        float2 v = h2[srcv[p] * 32 + l];
        acc.x += v.x; acc.y += v.y;
    }
    float inv = 1.f / fmaxf((float)(end - beg), 1.f);
    acc.x *= inv; acc.y *= inv;
    ((float2*)out)[w * 32 + l] = acc;
}

// SAGE epilogue: L2 normalize (+ optional relu). Warp per row.
__global__ void sage_post(const float* __restrict__ ml, const float* __restrict__ bl,
                          const float* __restrict__ xr, float* __restrict__ out, int dorelu) {
    int t = threadIdx.x;
    int w = t >> 5, l = t & 31;
    int n = blockIdx.x * 8 + w;
    float v0 = ml[n * 64 + l] + bl[l] + xr[n * 64 + l];
    float v1 = ml[n * 64 + 32 + l] + bl[32 + l] + xr[n * 64 + 32 + l];
    float ss = v0 * v0 + v1 * v1;
    for (int o = 16; o > 0; o >>= 1) ss += __shfl_xor_sync(0xffffffffu, ss, o);
    float inv = 1.f / fmaxf(sqrtf(ss), 1e-12f);
    float o0 = v0 * inv, o1 = v1 * inv;
    if (dorelu) { o0 = fmaxf(o0, 0.f); o1 = fmaxf(o1, 0.f); }
    out[n * 64 + l] = o0;
    out[n * 64 + 32 + l] = o1;
}

// ================= final combine =================
__global__ void combine_kernel(float4* __restrict__ out, const float* __restrict__ gate,
                               const float4* __restrict__ agg2, const float4* __restrict__ gagg2,
                               const float4* __restrict__ sout,
                               const float4* __restrict__ gcn_b2, const float4* __restrict__ gat_b2) {
    int i = blockIdx.x * 256 + threadIdx.x;   // NN*16 float4
    if (i >= NN * 16) return;
    int f = i & 15;
    float w0 = gate[0], w1 = gate[1], w2 = gate[2];
    float4 b0 = gcn_b2[f], b1 = gat_b2[f];
    float4 a = agg2[i], g = gagg2[i], s = sout[i];
    float4 o;
    o.x = w0 * (a.x + b0.x) + w1 * (g.x + b1.x) + w2 * s.x;
    o.y = w0 * (a.y + b0.y) + w1 * (g.y + b1.y) + w2 * s.y;
    o.z = w0 * (a.z + b0.z) + w1 * (g.z + b1.z) + w2 * s.z;
    o.w = w0 * (a.w + b0.w) + w1 * (g.w + b1.w) + w2 * s.w;
    out[i] = o;
}

// ================= launch =================
extern "C" void kernel_launch(void* const* d_in, const int* in_sizes, int n_in,
                              void* d_out, int out_size) {
    const float* x        = (const float*)d_in[0];
    const int*   ei       = (const int*)d_in[1];
    const float* gate_w1  = (const float*)d_in[2];
    const float* gate_b1  = (const float*)d_in[3];
    const float* gate_w2  = (const float*)d_in[4];
    const float* gate_b2  = (const float*)d_in[5];
    const float* gcn_w1   = (const float*)d_in[6];
    const float* gcn_b1   = (const float*)d_in[7];
    const float* bn_gamma = (const float*)d_in[8];
    const float* bn_beta  = (const float*)d_in[9];
    const float* gcn_w2   = (const float*)d_in[10];
    const float* gcn_b2   = (const float*)d_in[11];
    const float* gat_w1   = (const float*)d_in[12];
    const float* gat_as1  = (const float*)d_in[13];
    const float* gat_ad1  = (const float*)d_in[14];
    const float* gat_b1   = (const float*)d_in[15];
    const float* gat_w2   = (const float*)d_in[16];
    const float* gat_as2  = (const float*)d_in[17];
    const float* gat_ad2  = (const float*)d_in[18];
    const float* gat_b2   = (const float*)d_in[19];
    const float* sage_wl1 = (const float*)d_in[20];
    const float* sage_bl1 = (const float*)d_in[21];
    const float* sage_wr1 = (const float*)d_in[22];
    const float* sage_wl2 = (const float*)d_in[23];
    const float* sage_bl2 = (const float*)d_in[24];
    const float* sage_wr2 = (const float*)d_in[25];
    float* out = (float*)d_out;

    float* B = nullptr;
    cudaGetSymbolAddress((void**)&B, g_buf);

    int*   ecnt   = (int*)(B + O_ECNT);
    float* gsum   = B + O_GSUM;
    float* gate   = B + O_GATE;
    float* dis    = B + O_DIS;
    int*   off    = (int*)(B + O_OFF);
    int*   cur    = (int*)(B + O_CUR);
    int*   srcv   = (int*)(B + O_SRC);
    int*   bsum   = (int*)(B + O_BSUM);
    int*   boff   = (int*)(B + O_BOFF);
    float* gcnxh  = B + O_GCNXH;
    float* gcnh1  = B + O_GCNH1;
    float* gcnh2  = B + O_GCNH2;
    float* agg2   = B + O_AGG2;
    float* gath1  = B + O_GATH1;
    float* as1    = B + O_AS1;
    float* ad1    = B + O_AD1;
    float* gagg1  = B + O_GAGG1;
    float* gath2  = B + O_GATH2;
    float* as2    = B + O_AS2;
    float* ad2    = B + O_AD2;
    float* gagg2  = B + O_GAGG2;
    float* sxr    = B + O_SXR;
    float* smean  = B + O_SMEAN;
    float* sml    = B + O_SML;
    float* sh1    = B + O_SH1;
    float* smean2 = B + O_SMEAN2;
    float* sml2   = B + O_SML2;
    float* sxr2   = B + O_SXR2;
    float* sout   = B + O_SOUT;

    const int* rowp = ei;
    const int* colp = ei + NE;

    // zero edge counters + gate colsum accumulator (~200 KB)
    cudaMemsetAsync(B, 0, (size_t)ZEND * sizeof(float), 0);

    // ---- CSR build (by destination) ----
    degree_kernel<<<(NE + 255) / 256, 256>>>(colp, ecnt);
    scan_bsum<<<NB, 256>>>(ecnt, bsum);
    scan_boff<<<1, 256>>>(bsum, boff);
    scan_final<<<NB, 256>>>(ecnt, boff, off, cur);
    scatter_kernel<<<(NE + 255) / 256, 256>>>(rowp, colp, off, cur, srcv);
    dis_kernel<<<(NN + 255) / 256, 256>>>(off, dis);

    // ---- gate ----
    colsum_kernel<<<512, 256>>>(x, gsum);
    gate_kernel<<<1, 64>>>(gsum, gate, gate_w1, gate_b1, gate_w2, gate_b2);

    const int GB = (NN + 63) / 64;
    const int WPB = (NN * 32 + 255) / 256;   // warp-per-node grids

    // ---- feature transforms of x ----
    gemm_tile<<<dim3(GB, 1), 256>>>(x, gcn_w1, gcnxh, NN, 64, 64);
    gemm_tile<<<dim3(GB, 4), 256>>>(x, gat_w1, gath1, NN, 64, 256);
    gemm_tile<<<dim3(GB, 1), 256>>>(x, sage_wr1, sxr, NN, 64, 64);

    // ---- GCN ----
    gcn_node<1><<<WPB, 256>>>(off, srcv, dis, gcnxh, gcnh1, gcn_b1, bn_gamma, bn_beta);
    gemm_tile<<<dim3(GB, 1), 256>>>(gcnh1, gcn_w2, gcnh2, NN, 64, 64);
    gcn_node<0><<<WPB, 256>>>(off, srcv, dis, gcnh2, agg2, 0, 0, 0);

    // ---- GAT ----
    gat_att1<<<NN / 8, 256>>>(gath1, as1, ad1, gat_as1, gat_ad1);
    gat1_node<<<WPB, 256>>>(off, srcv, as1, ad1, gath1, gagg1, gat_b1);
    gemm_tile<<<dim3(GB, 1), 256>>>(gagg1, gat_w2, gath2, NN, 256, 64);
    gat_att2<<<NN / 8, 256>>>(gath2, as2, ad2, gat_as2, gat_ad2);
    gat2_node<<<WPB, 256>>>(off, srcv, as2, ad2, gath2, gagg2);

    // ---- SAGE ----
    sage_node<<<WPB, 256>>>(off, srcv, x, smean);
    gemm_tile<<<dim3(GB, 1), 256>>>(smean, sage_wl1, sml, NN, 64, 64);
    sage_post<<<NN / 8, 256>>>(sml, sage_bl1, sxr, sh1, 1);
    sage_node<<<WPB, 256>>>(off, srcv, sh1, smean2);
    gemm_tile<<<dim3(GB, 1), 256>>>(smean2, sage_wl2, sml2, NN, 64, 64);
    gemm_tile<<<dim3(GB, 1), 256>>>(sh1, sage_wr2, sxr2, NN, 64, 64);
    sage_post<<<NN / 8, 256>>>(sml2, sage_bl2, sxr2, sout, 0);

    // ---- combine ----
    combine_kernel<<<(NN * 16 + 255) / 256, 256>>>((float4*)out, gate,
                                                   (const float4*)agg2, (const float4*)gagg2,
                                                   (const float4*)sout,
                                                   (const float4*)gcn_b2, (const float4*)gat_b2);
}